// round 10
// baseline (speedup 1.0000x reference)
#include <cuda_runtime.h>
#include <math.h>

// Problem constants (fixed shapes from setup_inputs)
#define D 64
#define R 64
#define T 4096
#define B 8
#define NTOK (B * T)                  // 32768
#define TILES_PER_BATCH 4096
#define STRENGTH 0.1f
#define SC 0.17677669529663687f       // sqrt(2/64)

#define K1_CHUNKS 32                  // chunks of 128 tokens per batch
#define STRIDE 68                     // smem row stride (floats): 16B-aligned

// dynamic smem layout (floats) — R6 two-stage layout (57KB, eases co-residency)
#define OFF_W   0                     // [128][68] combined weights (persistent)
#define OFF_C   (128 * STRIDE)        // [64][68]  coords (per sub-pass)
#define OFF_P   (192 * STRIDE)        // [16][64]  per-token-group partials
#define OFF_B1  (OFF_P + 1024)        // [64]
#define OFF_W2  (OFF_B1 + 64)         // [64]
#define OFF_BR  (OFF_W2 + 64)         // [64]
#define SMEM_FLOATS (OFF_BR + 64)
#define SMEM_BYTES  (SMEM_FLOATS * 4) // 57088 B

// Scratch (device globals — no allocation)
__device__ float g_phi[(size_t)NTOK * R];        // 8 MB
__device__ float g_partial[B * K1_CHUNKS * R];
__device__ float g_phisum[B * R];

// ---------------------------------------------------------------------------
// K1 (per batch): tiled GEMM coords @ [w1^T | W], 128 tokens/block,
// two sub-passes. Thread tile: 4 tokens x 8 rows. (R6-verified core.)
// ---------------------------------------------------------------------------
__global__ __launch_bounds__(256) void k1_phi_mass(
    const float* __restrict__ coords, const float* __restrict__ w1,
    const float* __restrict__ b1, const float* __restrict__ w2,
    const float* __restrict__ b2, const float* __restrict__ W,
    const float* __restrict__ bR, const int bb)
{
    extern __shared__ float sm[];
    float* s_w    = sm + OFF_W;
    float* s_c    = sm + OFF_C;
    float* s_part = sm + OFF_P;
    float* s_b1   = sm + OFF_B1;
    float* s_w2   = sm + OFF_W2;
    float* s_bR   = sm + OFF_BR;

    const int tid = threadIdx.x;
    const int chunk = blockIdx.x;               // 0..31
    const int tokBase0 = bb * T + chunk * 128;

    for (int idx = tid; idx < 4096; idx += 256) {
        int r = idx >> 6, k = idx & 63;
        s_w[r * STRIDE + k] = w1[idx];
    }
    for (int idx = tid; idx < 4096; idx += 256) {
        int k = idx >> 6, r = idx & 63;
        s_w[(64 + r) * STRIDE + k] = W[idx];
    }
    if (tid < 64) { s_b1[tid] = b1[tid]; s_w2[tid] = w2[tid]; s_bR[tid] = bR[tid]; }

    const int tg = tid >> 4;
    const int rg = tid & 15;
    const float b2v = __ldg(b2);
    const float* cb = s_c + (tg * 4) * STRIDE;
    const float* wb = s_w + rg * STRIDE;

    float part[4] = {0.f, 0.f, 0.f, 0.f};

    for (int sub = 0; sub < 2; ++sub) {
        const int tokBase = tokBase0 + sub * 64;

        __syncthreads();
        for (int idx = tid; idx < 4096; idx += 256) {
            int t = idx >> 6, k = idx & 63;
            s_c[t * STRIDE + k] = coords[(size_t)(tokBase + t) * D + k];
        }
        __syncthreads();

        float acc[4][8];
        #pragma unroll
        for (int j = 0; j < 4; ++j)
            #pragma unroll
            for (int i = 0; i < 8; ++i) acc[j][i] = 0.f;

        #pragma unroll 4
        for (int k4 = 0; k4 < 16; ++k4) {
            float4 c[4], w[8];
            #pragma unroll
            for (int j = 0; j < 4; ++j)
                c[j] = *(const float4*)(cb + j * STRIDE + k4 * 4);
            #pragma unroll
            for (int i = 0; i < 8; ++i)
                w[i] = *(const float4*)(wb + i * 16 * STRIDE + k4 * 4);
            #pragma unroll
            for (int j = 0; j < 4; ++j)
                #pragma unroll
                for (int i = 0; i < 8; ++i) {
                    acc[j][i] = fmaf(c[j].x, w[i].x, acc[j][i]);
                    acc[j][i] = fmaf(c[j].y, w[i].y, acc[j][i]);
                    acc[j][i] = fmaf(c[j].z, w[i].z, acc[j][i]);
                    acc[j][i] = fmaf(c[j].w, w[i].w, acc[j][i]);
                }
        }

        #pragma unroll
        for (int j = 0; j < 4; ++j) {
            float mp = 0.f;
            #pragma unroll
            for (int i = 0; i < 4; ++i) {
                const int row = rg + i * 16;
                const float h = fmaxf(acc[j][i] + s_b1[row], 0.f);
                mp = fmaf(h, s_w2[row], mp);
            }
            mp += __shfl_xor_sync(0xffffffffu, mp, 8);
            mp += __shfl_xor_sync(0xffffffffu, mp, 4);
            mp += __shfl_xor_sync(0xffffffffu, mp, 2);
            mp += __shfl_xor_sync(0xffffffffu, mp, 1);
            const float x = mp + b2v;
            const float mass = fmaxf(x, 0.f) + __logf(1.f + __expf(-fabsf(x)));

            const size_t gbase = (size_t)(tokBase + tg * 4 + j) * R;
            #pragma unroll
            for (int i = 0; i < 4; ++i) {
                const int row = rg + i * 16;
                const float ph = SC * __cosf(acc[j][i + 4] + s_bR[row]);
                g_phi[gbase + row] = ph;
                part[i] = fmaf(mass, ph, part[i]);
            }
        }
    }

    __syncthreads();
    #pragma unroll
    for (int i = 0; i < 4; ++i)
        s_part[tg * 64 + rg + i * 16] = part[i];
    __syncthreads();

    if (tid < 64) {
        float s = 0.f;
        #pragma unroll
        for (int t = 0; t < 16; ++t) s += s_part[t * 64 + tid];
        g_partial[(bb * K1_CHUNKS + chunk) * 64 + tid] = s;
    }
}

// ---------------------------------------------------------------------------
// K2 (per batch): phisum[bb][r] = sum over 32 chunk partials
// ---------------------------------------------------------------------------
__global__ void k2_phisum(const int bb)
{
    const int r = threadIdx.x;        // 64 threads
    float s = 0.f;
    #pragma unroll
    for (int c = 0; c < K1_CHUNKS; ++c)
        s += g_partial[(bb * K1_CHUNKS + c) * 64 + r];
    g_phisum[bb * 64 + r] = s;
}

// ---------------------------------------------------------------------------
// K4 (per batch): full-line 128 MiB stream with fused grav + diagonal add.
// Block per tile; warp 0 computes grav while loads are in flight. (R8 core.)
// ---------------------------------------------------------------------------
__global__ __launch_bounds__(256) void k4_copy(const float4* __restrict__ G4,
                                               float4* __restrict__ O4,
                                               const int bb)
{
    __shared__ float s_gv;
    const unsigned tile = (unsigned)bb * TILES_PER_BATCH + blockIdx.x;
    const size_t base = (size_t)tile * 1024;
    const unsigned t = threadIdx.x;

    float4 v[4];
    #pragma unroll
    for (int k = 0; k < 4; ++k)
        v[k] = __ldcs(G4 + base + k * 256u + t);

    if (t < 32) {
        const float* ph = g_phi + (size_t)tile * R;
        const float* ps = g_phisum + bb * 64;
        float x = fmaf(ph[t], ps[t], ph[t + 32] * ps[t + 32]);
        x += __shfl_xor_sync(0xffffffffu, x, 16);
        x += __shfl_xor_sync(0xffffffffu, x, 8);
        x += __shfl_xor_sync(0xffffffffu, x, 4);
        x += __shfl_xor_sync(0xffffffffu, x, 2);
        x += __shfl_xor_sync(0xffffffffu, x, 1);
        if (t == 0) s_gv = STRENGTH * x;
    }
    __syncthreads();
    const float gv = s_gv;

    #pragma unroll
    for (int k = 0; k < 4; ++k) {
        const unsigned within = k * 256u + t;
        const int i  = (int)(within >> 4);
        const int j0 = (int)((within & 15u) << 2);
        const int d  = i - j0;
        if ((unsigned)d < 4u) {
            if      (d == 0) v[k].x += gv;
            else if (d == 1) v[k].y += gv;
            else if (d == 2) v[k].z += gv;
            else             v[k].w += gv;
        }
        __stcs(O4 + base + within, v[k]);
    }
}

// ---------------------------------------------------------------------------
// Batch-pipelined schedule: high-priority side stream computes phisum[b]
// per batch; main stream streams batch b's 128 MiB as soon as e_b fires.
// (Handles intentionally not destroyed: they participate in graph capture.)
// ---------------------------------------------------------------------------
extern "C" void kernel_launch(void* const* d_in, const int* in_sizes, int n_in,
                              void* d_out, int out_size)
{
    const float* G      = (const float*)d_in[0];
    const float* coords = (const float*)d_in[1];
    const float* w1     = (const float*)d_in[2];
    const float* b1     = (const float*)d_in[3];
    const float* w2     = (const float*)d_in[4];
    const float* b2     = (const float*)d_in[5];
    const float* W      = (const float*)d_in[6];
    const float* bR     = (const float*)d_in[7];
    float* out = (float*)d_out;

    cudaFuncSetAttribute(k1_phi_mass,
                         cudaFuncAttributeMaxDynamicSharedMemorySize, SMEM_BYTES);

    int prLow = 0, prHigh = 0;
    cudaDeviceGetStreamPriorityRange(&prLow, &prHigh);

    cudaStream_t sA;
    cudaStreamCreateWithPriority(&sA, cudaStreamNonBlocking, prHigh);

    cudaEvent_t eFork, eB[B];
    cudaEventCreateWithFlags(&eFork, cudaEventDisableTiming);
    for (int b = 0; b < B; ++b)
        cudaEventCreateWithFlags(&eB[b], cudaEventDisableTiming);

    cudaEventRecord(eFork, 0);
    cudaStreamWaitEvent(sA, eFork, 0);                 // fork

    for (int b = 0; b < B; ++b) {
        k1_phi_mass<<<K1_CHUNKS, 256, SMEM_BYTES, sA>>>(coords, w1, b1, w2,
                                                        b2, W, bR, b);
        k2_phisum<<<1, 64, 0, sA>>>(b);
        cudaEventRecord(eB[b], sA);
    }

    for (int b = 0; b < B; ++b) {
        cudaStreamWaitEvent(0, eB[b], 0);              // join point for batch b
        k4_copy<<<TILES_PER_BATCH, 256>>>((const float4*)G, (float4*)out, b);
    }
}

// round 11
// speedup vs baseline: 1.5392x; 1.5392x over previous
#include <cuda_runtime.h>
#include <math.h>

// Problem constants (fixed shapes from setup_inputs)
#define D 64
#define R 64
#define T 4096
#define B 8
#define NTOK (B * T)                  // 32768
#define TILES_PER_BATCH 4096
#define STRENGTH 0.1f
#define SC 0.17677669529663687f       // sqrt(2/64)

#define K1_BLOCKS 256                 // 8 batches * 32 chunks of 128 tokens
#define K1_CHUNKS 32                  // per batch
#define STRIDE 68                     // smem row stride (floats): 16B-aligned

// dynamic smem layout (floats)
#define OFF_W   0                     // [128][68] combined weights (persistent)
#define OFF_C   (128 * STRIDE)        // [64][68]  coords (per sub-pass)
#define OFF_P   (192 * STRIDE)        // [16][64]  per-token-group partials
#define OFF_B1  (OFF_P + 1024)        // [64]
#define OFF_W2  (OFF_B1 + 64)         // [64]
#define OFF_BR  (OFF_W2 + 64)         // [64]
#define SMEM_FLOATS (OFF_BR + 64)
#define SMEM_BYTES  (SMEM_FLOATS * 4) // 57088 B -> 2 CTAs/SM

// Scratch (device globals — no allocation)
__device__ float g_phi[(size_t)NTOK * R];        // 8 MB (L2-resident at use)
__device__ float g_partial[K1_BLOCKS * R];
__device__ float g_phisum[B * R];
__device__ unsigned g_done;                      // zero-initialized; self-resets

// ---------------------------------------------------------------------------
// K1: tiled GEMM coords @ [w1^T | W], 128 tokens/block, two sub-passes.
// Thread tile: 4 tokens (tg) x 8 rows (rg + 16*i; i<4 = w1, i>=4 = W).
// Last-finishing block reduces all chunk partials -> g_phisum (deterministic).
// ---------------------------------------------------------------------------
__global__ __launch_bounds__(256) void k1_phi_mass(
    const float* __restrict__ coords, const float* __restrict__ w1,
    const float* __restrict__ b1, const float* __restrict__ w2,
    const float* __restrict__ b2, const float* __restrict__ W,
    const float* __restrict__ bR)
{
    extern __shared__ float sm[];
    float* s_w    = sm + OFF_W;
    float* s_c    = sm + OFF_C;
    float* s_part = sm + OFF_P;
    float* s_b1   = sm + OFF_B1;
    float* s_w2   = sm + OFF_W2;
    float* s_bR   = sm + OFF_BR;
    __shared__ bool s_last;

    const int tid = threadIdx.x;
    const int bb = blockIdx.x >> 5, chunk = blockIdx.x & 31;
    const int tokBase0 = bb * T + chunk * 128;

    // --- stage weights (float4 where layout permits) ---
    {
        const float4* w1f4 = (const float4*)w1;
        for (int idx = tid; idx < 1024; idx += 256) {
            int r = idx >> 4, k4i = idx & 15;
            *(float4*)(s_w + r * STRIDE + k4i * 4) = w1f4[idx];
        }
        for (int idx = tid; idx < 4096; idx += 256) {   // W transpose: scalar
            int k = idx >> 6, r = idx & 63;
            s_w[(64 + r) * STRIDE + k] = W[idx];
        }
    }
    if (tid < 64) { s_b1[tid] = b1[tid]; s_w2[tid] = w2[tid]; s_bR[tid] = bR[tid]; }

    const int tg = tid >> 4;
    const int rg = tid & 15;
    const float b2v = __ldg(b2);
    const float* cb = s_c + (tg * 4) * STRIDE;
    const float* wb = s_w + rg * STRIDE;

    float part[4] = {0.f, 0.f, 0.f, 0.f};

    for (int sub = 0; sub < 2; ++sub) {
        const int tokBase = tokBase0 + sub * 64;

        __syncthreads();
        {
            const float4* cf4 = (const float4*)(coords + (size_t)tokBase * D);
            for (int idx = tid; idx < 1024; idx += 256) {
                int t = idx >> 4, k4i = idx & 15;
                *(float4*)(s_c + t * STRIDE + k4i * 4) = cf4[idx];
            }
        }
        __syncthreads();

        float acc[4][8];
        #pragma unroll
        for (int j = 0; j < 4; ++j)
            #pragma unroll
            for (int i = 0; i < 8; ++i) acc[j][i] = 0.f;

        #pragma unroll 4
        for (int k4 = 0; k4 < 16; ++k4) {
            float4 c[4], w[8];
            #pragma unroll
            for (int j = 0; j < 4; ++j)
                c[j] = *(const float4*)(cb + j * STRIDE + k4 * 4);
            #pragma unroll
            for (int i = 0; i < 8; ++i)
                w[i] = *(const float4*)(wb + i * 16 * STRIDE + k4 * 4);
            #pragma unroll
            for (int j = 0; j < 4; ++j)
                #pragma unroll
                for (int i = 0; i < 8; ++i) {
                    acc[j][i] = fmaf(c[j].x, w[i].x, acc[j][i]);
                    acc[j][i] = fmaf(c[j].y, w[i].y, acc[j][i]);
                    acc[j][i] = fmaf(c[j].z, w[i].z, acc[j][i]);
                    acc[j][i] = fmaf(c[j].w, w[i].w, acc[j][i]);
                }
        }

        // --- epilogue (registers + shfl only) ---
        #pragma unroll
        for (int j = 0; j < 4; ++j) {
            float mp = 0.f;
            #pragma unroll
            for (int i = 0; i < 4; ++i) {
                const int row = rg + i * 16;
                const float h = fmaxf(acc[j][i] + s_b1[row], 0.f);
                mp = fmaf(h, s_w2[row], mp);
            }
            mp += __shfl_xor_sync(0xffffffffu, mp, 8);
            mp += __shfl_xor_sync(0xffffffffu, mp, 4);
            mp += __shfl_xor_sync(0xffffffffu, mp, 2);
            mp += __shfl_xor_sync(0xffffffffu, mp, 1);
            const float x = mp + b2v;
            const float mass = fmaxf(x, 0.f) + __logf(1.f + __expf(-fabsf(x)));

            const size_t gbase = (size_t)(tokBase + tg * 4 + j) * R;
            #pragma unroll
            for (int i = 0; i < 4; ++i) {
                const int row = rg + i * 16;
                const float ph = SC * __cosf(acc[j][i + 4] + s_bR[row]);
                g_phi[gbase + row] = ph;
                part[i] = fmaf(mass, ph, part[i]);
            }
        }
    }

    __syncthreads();
    #pragma unroll
    for (int i = 0; i < 4; ++i)
        s_part[tg * 64 + rg + i * 16] = part[i];
    __syncthreads();

    if (tid < 64) {
        float s = 0.f;
        #pragma unroll
        for (int t = 0; t < 16; ++t) s += s_part[t * 64 + tid];
        g_partial[blockIdx.x * 64 + tid] = s;
    }

    // --- last block reduces partials -> phisum (deterministic fixed order) ---
    __threadfence();
    if (tid == 0)
        s_last = (atomicAdd(&g_done, 1u) == K1_BLOCKS - 1);
    __syncthreads();
    if (s_last) {
        // tid -> (batch, r): 256 threads cover 4 batches per pass, 2 passes
        for (int half = 0; half < 2; ++half) {
            const int b = half * 4 + (tid >> 6);
            const int r = tid & 63;
            float s = 0.f;
            #pragma unroll
            for (int c = 0; c < K1_CHUNKS; ++c)
                s += g_partial[(b * K1_CHUNKS + c) * 64 + r];
            g_phisum[b * 64 + r] = s;
        }
        if (tid == 0) g_done = 0;     // reset for next graph replay
    }
}

// ---------------------------------------------------------------------------
// K4: full-line 1 GiB stream of G with fused grav compute + diagonal add.
// Block per tile; warp 0 computes grav while the 4 G loads are in flight.
// ---------------------------------------------------------------------------
__global__ __launch_bounds__(256) void k4_copy(const float4* __restrict__ G4,
                                               float4* __restrict__ O4)
{
    __shared__ float s_gv;
    const unsigned tile = blockIdx.x;
    const size_t base = (size_t)tile * 1024;
    const unsigned t = threadIdx.x;

    float4 v[4];
    #pragma unroll
    for (int k = 0; k < 4; ++k)
        v[k] = __ldcs(G4 + base + k * 256u + t);

    if (t < 32) {
        const unsigned bb = tile >> 12;                // 4096 tiles per batch
        const float* ph = g_phi + (size_t)tile * R;
        const float* ps = g_phisum + bb * 64;
        float x = fmaf(ph[t], ps[t], ph[t + 32] * ps[t + 32]);
        x += __shfl_xor_sync(0xffffffffu, x, 16);
        x += __shfl_xor_sync(0xffffffffu, x, 8);
        x += __shfl_xor_sync(0xffffffffu, x, 4);
        x += __shfl_xor_sync(0xffffffffu, x, 2);
        x += __shfl_xor_sync(0xffffffffu, x, 1);
        if (t == 0) s_gv = STRENGTH * x;
    }
    __syncthreads();
    const float gv = s_gv;

    #pragma unroll
    for (int k = 0; k < 4; ++k) {
        const unsigned within = k * 256u + t;
        const int i  = (int)(within >> 4);
        const int j0 = (int)((within & 15u) << 2);
        const int d  = i - j0;
        if ((unsigned)d < 4u) {
            if      (d == 0) v[k].x += gv;
            else if (d == 1) v[k].y += gv;
            else if (d == 2) v[k].z += gv;
            else             v[k].w += gv;
        }
        __stcs(O4 + base + within, v[k]);
    }
}

// ---------------------------------------------------------------------------
extern "C" void kernel_launch(void* const* d_in, const int* in_sizes, int n_in,
                              void* d_out, int out_size)
{
    const float* G      = (const float*)d_in[0];
    const float* coords = (const float*)d_in[1];
    const float* w1     = (const float*)d_in[2];
    const float* b1     = (const float*)d_in[3];
    const float* w2     = (const float*)d_in[4];
    const float* b2     = (const float*)d_in[5];
    const float* W      = (const float*)d_in[6];
    const float* bR     = (const float*)d_in[7];
    float* out = (float*)d_out;

    cudaFuncSetAttribute(k1_phi_mass,
                         cudaFuncAttributeMaxDynamicSharedMemorySize, SMEM_BYTES);

    k1_phi_mass<<<K1_BLOCKS, 256, SMEM_BYTES>>>(coords, w1, b1, w2, b2, W, bR);
    k4_copy<<<NTOK, 256>>>((const float4*)G, (float4*)out);
}

// round 13
// speedup vs baseline: 1.5462x; 1.0045x over previous
#include <cuda_runtime.h>
#include <math.h>

// Problem constants (fixed shapes from setup_inputs)
#define D 64
#define R 64
#define T 4096
#define B 8
#define NTOK (B * T)                  // 32768
#define STRENGTH 0.1f
#define SC 0.17677669529663687f       // sqrt(2/64)

#define K1_BLOCKS 256                 // 8 batches * 32 chunks of 128 tokens
#define K1_CHUNKS 32                  // per batch
#define STRIDE 68                     // smem row stride (floats): 16B-aligned

// dynamic smem layout (floats)
#define OFF_W   0                     // [128][68] combined weights (persistent)
#define OFF_C   (128 * STRIDE)        // [64][68]  coords (per sub-pass)
#define OFF_P   (192 * STRIDE)        // [16][64]  per-token-group partials
#define OFF_B1  (OFF_P + 1024)        // [64]
#define OFF_W2  (OFF_B1 + 64)         // [64]
#define OFF_BR  (OFF_W2 + 64)         // [64]
#define SMEM_FLOATS (OFF_BR + 64)
#define SMEM_BYTES  (SMEM_FLOATS * 4) // 57088 B -> 2 CTAs/SM

// Scratch (device globals — no allocation)
__device__ float g_phi[(size_t)NTOK * R];        // 8 MB (L2-resident at use)
__device__ float g_partial[K1_BLOCKS * R];
__device__ float g_phisum[B * R];
__device__ unsigned g_done;                      // zero-initialized; self-resets

// ---------------------------------------------------------------------------
// K1: tiled GEMM coords @ [w1^T | W], 128 tokens/block, two sub-passes.
// Thread tile: 4 tokens (tg) x 8 rows (rg + 16*i; i<4 = w1, i>=4 = W).
// Last-finishing block reduces all chunk partials -> g_phisum (deterministic).
// (Unchanged from R11 — verified 33 us.)
// ---------------------------------------------------------------------------
__global__ __launch_bounds__(256) void k1_phi_mass(
    const float* __restrict__ coords, const float* __restrict__ w1,
    const float* __restrict__ b1, const float* __restrict__ w2,
    const float* __restrict__ b2, const float* __restrict__ W,
    const float* __restrict__ bR)
{
    extern __shared__ float sm[];
    float* s_w    = sm + OFF_W;
    float* s_c    = sm + OFF_C;
    float* s_part = sm + OFF_P;
    float* s_b1   = sm + OFF_B1;
    float* s_w2   = sm + OFF_W2;
    float* s_bR   = sm + OFF_BR;
    __shared__ bool s_last;

    const int tid = threadIdx.x;
    const int bb = blockIdx.x >> 5, chunk = blockIdx.x & 31;
    const int tokBase0 = bb * T + chunk * 128;

    // --- stage weights (float4 where layout permits) ---
    {
        const float4* w1f4 = (const float4*)w1;
        for (int idx = tid; idx < 1024; idx += 256) {
            int r = idx >> 4, k4i = idx & 15;
            *(float4*)(s_w + r * STRIDE + k4i * 4) = w1f4[idx];
        }
        for (int idx = tid; idx < 4096; idx += 256) {   // W transpose: scalar
            int k = idx >> 6, r = idx & 63;
            s_w[(64 + r) * STRIDE + k] = W[idx];
        }
    }
    if (tid < 64) { s_b1[tid] = b1[tid]; s_w2[tid] = w2[tid]; s_bR[tid] = bR[tid]; }

    const int tg = tid >> 4;
    const int rg = tid & 15;
    const float b2v = __ldg(b2);
    const float* cb = s_c + (tg * 4) * STRIDE;
    const float* wb = s_w + rg * STRIDE;

    float part[4] = {0.f, 0.f, 0.f, 0.f};

    for (int sub = 0; sub < 2; ++sub) {
        const int tokBase = tokBase0 + sub * 64;

        __syncthreads();
        {
            const float4* cf4 = (const float4*)(coords + (size_t)tokBase * D);
            for (int idx = tid; idx < 1024; idx += 256) {
                int t = idx >> 4, k4i = idx & 15;
                *(float4*)(s_c + t * STRIDE + k4i * 4) = cf4[idx];
            }
        }
        __syncthreads();

        float acc[4][8];
        #pragma unroll
        for (int j = 0; j < 4; ++j)
            #pragma unroll
            for (int i = 0; i < 8; ++i) acc[j][i] = 0.f;

        #pragma unroll 4
        for (int k4 = 0; k4 < 16; ++k4) {
            float4 c[4], w[8];
            #pragma unroll
            for (int j = 0; j < 4; ++j)
                c[j] = *(const float4*)(cb + j * STRIDE + k4 * 4);
            #pragma unroll
            for (int i = 0; i < 8; ++i)
                w[i] = *(const float4*)(wb + i * 16 * STRIDE + k4 * 4);
            #pragma unroll
            for (int j = 0; j < 4; ++j)
                #pragma unroll
                for (int i = 0; i < 8; ++i) {
                    acc[j][i] = fmaf(c[j].x, w[i].x, acc[j][i]);
                    acc[j][i] = fmaf(c[j].y, w[i].y, acc[j][i]);
                    acc[j][i] = fmaf(c[j].z, w[i].z, acc[j][i]);
                    acc[j][i] = fmaf(c[j].w, w[i].w, acc[j][i]);
                }
        }

        // --- epilogue (registers + shfl only) ---
        #pragma unroll
        for (int j = 0; j < 4; ++j) {
            float mp = 0.f;
            #pragma unroll
            for (int i = 0; i < 4; ++i) {
                const int row = rg + i * 16;
                const float h = fmaxf(acc[j][i] + s_b1[row], 0.f);
                mp = fmaf(h, s_w2[row], mp);
            }
            mp += __shfl_xor_sync(0xffffffffu, mp, 8);
            mp += __shfl_xor_sync(0xffffffffu, mp, 4);
            mp += __shfl_xor_sync(0xffffffffu, mp, 2);
            mp += __shfl_xor_sync(0xffffffffu, mp, 1);
            const float x = mp + b2v;
            const float mass = fmaxf(x, 0.f) + __logf(1.f + __expf(-fabsf(x)));

            const size_t gbase = (size_t)(tokBase + tg * 4 + j) * R;
            #pragma unroll
            for (int i = 0; i < 4; ++i) {
                const int row = rg + i * 16;
                const float ph = SC * __cosf(acc[j][i + 4] + s_bR[row]);
                g_phi[gbase + row] = ph;
                part[i] = fmaf(mass, ph, part[i]);
            }
        }
    }

    __syncthreads();
    #pragma unroll
    for (int i = 0; i < 4; ++i)
        s_part[tg * 64 + rg + i * 16] = part[i];
    __syncthreads();

    if (tid < 64) {
        float s = 0.f;
        #pragma unroll
        for (int t = 0; t < 16; ++t) s += s_part[t * 64 + tid];
        g_partial[blockIdx.x * 64 + tid] = s;
    }

    // --- last block reduces partials -> phisum (deterministic fixed order) ---
    __threadfence();
    if (tid == 0)
        s_last = (atomicAdd(&g_done, 1u) == K1_BLOCKS - 1);
    __syncthreads();
    if (s_last) {
        for (int half = 0; half < 2; ++half) {
            const int b = half * 4 + (tid >> 6);
            const int r = tid & 63;
            float s = 0.f;
            #pragma unroll
            for (int c = 0; c < K1_CHUNKS; ++c)
                s += g_partial[(b * K1_CHUNKS + c) * 64 + r];
            g_phisum[b * 64 + r] = s;
        }
        if (tid == 0) g_done = 0;     // reset for next graph replay
    }
}

// ---------------------------------------------------------------------------
// K4: full-line 1 GiB stream of G with fused grav + diagonal add.
// Per-warp grav: every warp redundantly computes the phi dot (L1-hit after
// warp 0 installs the 256B line) — no __syncthreads, no smem broadcast.
// ---------------------------------------------------------------------------
__global__ __launch_bounds__(256) void k4_copy(const float4* __restrict__ G4,
                                               float4* __restrict__ O4)
{
    const unsigned tile = blockIdx.x;
    const size_t base = (size_t)tile * 1024;
    const unsigned t = threadIdx.x;
    const int lane = (int)(t & 31u);

    float4 v[4];
    #pragma unroll
    for (int k = 0; k < 4; ++k)
        v[k] = __ldcs(G4 + base + k * 256u + t);

    // per-warp grav reduce (identical order across warps -> deterministic)
    const unsigned bb = tile >> 12;                    // 4096 tiles per batch
    const float* ph = g_phi + (size_t)tile * R;
    const float* ps = g_phisum + bb * 64;
    float x = fmaf(ph[lane], ps[lane], ph[lane + 32] * ps[lane + 32]);
    x += __shfl_xor_sync(0xffffffffu, x, 16);
    x += __shfl_xor_sync(0xffffffffu, x, 8);
    x += __shfl_xor_sync(0xffffffffu, x, 4);
    x += __shfl_xor_sync(0xffffffffu, x, 2);
    x += __shfl_xor_sync(0xffffffffu, x, 1);
    const float gv = STRENGTH * x;                     // warp-uniform

    #pragma unroll
    for (int k = 0; k < 4; ++k) {
        const unsigned within = k * 256u + t;
        const int i  = (int)(within >> 4);
        const int j0 = (int)((within & 15u) << 2);
        const int d  = i - j0;
        if ((unsigned)d < 4u) {
            if      (d == 0) v[k].x += gv;
            else if (d == 1) v[k].y += gv;
            else if (d == 2) v[k].z += gv;
            else             v[k].w += gv;
        }
        __stcs(O4 + base + within, v[k]);
    }
}

// ---------------------------------------------------------------------------
extern "C" void kernel_launch(void* const* d_in, const int* in_sizes, int n_in,
                              void* d_out, int out_size)
{
    const float* G      = (const float*)d_in[0];
    const float* coords = (const float*)d_in[1];
    const float* w1     = (const float*)d_in[2];
    const float* b1     = (const float*)d_in[3];
    const float* w2     = (const float*)d_in[4];
    const float* b2     = (const float*)d_in[5];
    const float* W      = (const float*)d_in[6];
    const float* bR     = (const float*)d_in[7];
    float* out = (float*)d_out;

    cudaFuncSetAttribute(k1_phi_mass,
                         cudaFuncAttributeMaxDynamicSharedMemorySize, SMEM_BYTES);

    k1_phi_mass<<<K1_BLOCKS, 256, SMEM_BYTES>>>(coords, w1, b1, w2, b2, W, bR);
    k4_copy<<<NTOK, 256>>>((const float4*)G, (float4*)out);
}